// round 1
// baseline (speedup 1.0000x reference)
#include <cuda_runtime.h>
#include <math.h>

// Problem constants
#define U_    128          // LSTM units
#define NG    512          // 4*U (gate width)
#define T_    512          // timesteps
#define B_    256          // batch
#define F_    64           // input features
#define OUT_  6            // dense head
#define SMEM_COLS 416      // Rt columns resident in SMEM (warp-aligned; rest via L2)

// ---------------- scratch (static device allocations only) ----------------
__device__ float g_xw[(size_t)B_ * T_ * NG];   // per-layer input projection [B*T, 512] (268 MB)
__device__ float g_h [(size_t)B_ * T_ * U_];   // per-layer hidden sequence  [B*T, 128] (67 MB)
__device__ float g_RT[NG * U_];                // transposed recurrent matrix [512,128]

// ---------------- R transpose: R[U,4U] -> RT[4U,U] ----------------
__global__ void k_transpose_R(const float* __restrict__ R) {
    int j = blockIdx.x;       // output row (gate col) 0..511
    int k = threadIdx.x;      // 0..127
    g_RT[j * U_ + k] = R[k * NG + j];
}

// ---------------- GEMM: g_xw[M,512] = A[M,K] @ W[K,512] + bias ----------------
#define BM 64
#define BN 64
#define BK 16
__global__ __launch_bounds__(256) void k_gemm_xw(const float* __restrict__ Ain,
                                                 const float* __restrict__ W,
                                                 const float* __restrict__ bias,
                                                 int K) {
    const float* A = Ain ? Ain : g_h;   // nullptr => read previous layer's hidden sequence
    __shared__ float As[BK][BM];
    __shared__ float Bs[BK][BN + 4];
    const int brow = blockIdx.y * BM;
    const int bcol = blockIdx.x * BN;
    const int tid = threadIdx.x;
    const int tx = tid & 15, ty = tid >> 4;   // 16x16 thread grid, 4x4 micro tiles

    float acc[4][4] = {};
    for (int k0 = 0; k0 < K; k0 += BK) {
        #pragma unroll
        for (int i = tid; i < BK * BM; i += 256) {
            int m = i >> 4, k = i & 15;
            As[k][m] = A[(size_t)(brow + m) * K + (k0 + k)];
        }
        #pragma unroll
        for (int i = tid; i < BK * BN; i += 256) {
            int k = i >> 6, n = i & 63;
            Bs[k][n] = W[(size_t)(k0 + k) * NG + (bcol + n)];
        }
        __syncthreads();
        #pragma unroll
        for (int k = 0; k < BK; k++) {
            float a0 = As[k][ty * 4 + 0], a1 = As[k][ty * 4 + 1];
            float a2 = As[k][ty * 4 + 2], a3 = As[k][ty * 4 + 3];
            float4 bv = *reinterpret_cast<const float4*>(&Bs[k][tx * 4]);
            acc[0][0] = fmaf(a0, bv.x, acc[0][0]); acc[0][1] = fmaf(a0, bv.y, acc[0][1]);
            acc[0][2] = fmaf(a0, bv.z, acc[0][2]); acc[0][3] = fmaf(a0, bv.w, acc[0][3]);
            acc[1][0] = fmaf(a1, bv.x, acc[1][0]); acc[1][1] = fmaf(a1, bv.y, acc[1][1]);
            acc[1][2] = fmaf(a1, bv.z, acc[1][2]); acc[1][3] = fmaf(a1, bv.w, acc[1][3]);
            acc[2][0] = fmaf(a2, bv.x, acc[2][0]); acc[2][1] = fmaf(a2, bv.y, acc[2][1]);
            acc[2][2] = fmaf(a2, bv.z, acc[2][2]); acc[2][3] = fmaf(a2, bv.w, acc[2][3]);
            acc[3][0] = fmaf(a3, bv.x, acc[3][0]); acc[3][1] = fmaf(a3, bv.y, acc[3][1]);
            acc[3][2] = fmaf(a3, bv.z, acc[3][2]); acc[3][3] = fmaf(a3, bv.w, acc[3][3]);
        }
        __syncthreads();
    }
    #pragma unroll
    for (int i = 0; i < 4; i++) {
        size_t row = (size_t)(brow + ty * 4 + i);
        #pragma unroll
        for (int j = 0; j < 4; j++) {
            int col = bcol + tx * 4 + j;
            g_xw[row * NG + col] = acc[i][j] + bias[col];
        }
    }
}

// ---------------- LSTM scan: one CTA owns 2 batch rows for all T steps ----------------
// SMEM: Rt cols [0,416) resident (213KB); cols [416,512) read from L2 each step.
// Thread = one gate column (512 threads). Per step:
//   z[m][col] = xw[m][t][col] + sum_k h[m][k] * Rt[col][k]  (fp32, FMA-bound)
#define LSTM_SMEM_FLOATS (SMEM_COLS * U_ + 2 * U_ + 2 * U_ + 2 * NG)
#define LSTM_SMEM_BYTES  (LSTM_SMEM_FLOATS * 4)

__global__ __launch_bounds__(512) void k_lstm() {
    extern __shared__ float smem[];
    float* sR   = smem;                       // [SMEM_COLS][128]
    float* sh   = sR + SMEM_COLS * U_;        // [2][128]
    float* sc   = sh + 2 * U_;                // [2][128]
    float* sact = sc + 2 * U_;                // [2][512] activated gates

    const int tid = threadIdx.x;              // gate column
    const int b0 = blockIdx.x * 2;

    for (int i = tid; i < SMEM_COLS * U_; i += 512) sR[i] = g_RT[i];
    if (tid < 2 * U_) { sh[tid] = 0.f; sc[tid] = 0.f; }
    __syncthreads();

    const float4* sh4 = reinterpret_cast<const float4*>(sh);
    const size_t xw0base = (size_t)b0 * T_ * NG;
    const size_t xw1base = (size_t)(b0 + 1) * T_ * NG;
    const bool in_smem = (tid < SMEM_COLS);
    const float4* rp = in_smem
        ? reinterpret_cast<const float4*>(sR + tid * U_)
        : reinterpret_cast<const float4*>(g_RT + tid * U_);

    for (int t = 0; t < T_; t++) {
        float acc0 = __ldcs(&g_xw[xw0base + (size_t)t * NG + tid]);
        float acc1 = __ldcs(&g_xw[xw1base + (size_t)t * NG + tid]);

        if (in_smem) {
            #pragma unroll
            for (int k = 0; k < U_ / 4; k++) {
                float4 r  = rp[k];
                float4 h0 = sh4[k];
                float4 h1 = sh4[k + U_ / 4];
                acc0 = fmaf(h0.x, r.x, acc0); acc0 = fmaf(h0.y, r.y, acc0);
                acc0 = fmaf(h0.z, r.z, acc0); acc0 = fmaf(h0.w, r.w, acc0);
                acc1 = fmaf(h1.x, r.x, acc1); acc1 = fmaf(h1.y, r.y, acc1);
                acc1 = fmaf(h1.z, r.z, acc1); acc1 = fmaf(h1.w, r.w, acc1);
            }
        } else {
            #pragma unroll
            for (int k = 0; k < U_ / 4; k++) {
                float4 r  = rp[k];        // L2-resident (Rt is 256KB, hot)
                float4 h0 = sh4[k];
                float4 h1 = sh4[k + U_ / 4];
                acc0 = fmaf(h0.x, r.x, acc0); acc0 = fmaf(h0.y, r.y, acc0);
                acc0 = fmaf(h0.z, r.z, acc0); acc0 = fmaf(h0.w, r.w, acc0);
                acc1 = fmaf(h1.x, r.x, acc1); acc1 = fmaf(h1.y, r.y, acc1);
                acc1 = fmaf(h1.z, r.z, acc1); acc1 = fmaf(h1.w, r.w, acc1);
            }
        }

        // gate activations (i,f,o: sigmoid; g: tanh). Warp-uniform branch (gate = tid>>7).
        float a0, a1;
        if ((tid >> 7) == 2) {
            a0 = tanhf(acc0); a1 = tanhf(acc1);
        } else {
            a0 = 1.f / (1.f + expf(-acc0));
            a1 = 1.f / (1.f + expf(-acc1));
        }
        sact[tid] = a0;
        sact[NG + tid] = a1;
        __syncthreads();

        if (tid < 2 * U_) {
            int m = tid >> 7, u = tid & (U_ - 1);
            const float* s = sact + m * NG;
            float iv = s[u], fv = s[U_ + u], gv = s[2 * U_ + u], ov = s[3 * U_ + u];
            float c = fmaf(fv, sc[tid], iv * gv);
            float h = ov * tanhf(c);
            sc[tid] = c;
            sh[tid] = h;
            g_h[((size_t)(b0 + m) * T_ + t) * U_ + u] = h;
        }
        __syncthreads();
    }
}

// ---------------- dense head: out[256,6] = h_last @ Wd + bd ----------------
__global__ void k_dense(const float* __restrict__ Wd, const float* __restrict__ bd,
                        float* __restrict__ out) {
    int idx = blockIdx.x * 256 + threadIdx.x;
    if (idx >= B_ * OUT_) return;
    int b = idx / OUT_, j = idx % OUT_;
    const float* hrow = &g_h[((size_t)b * T_ + (T_ - 1)) * U_];
    float s = bd[j];
    #pragma unroll
    for (int k = 0; k < U_; k++) s = fmaf(hrow[k], Wd[k * OUT_ + j], s);
    out[idx] = s;
}

// ---------------- launch ----------------
extern "C" void kernel_launch(void* const* d_in, const int* in_sizes, int n_in,
                              void* d_out, int out_size) {
    const float* x  = (const float*)d_in[0];
    const float* W0 = (const float*)d_in[1];
    const float* R0 = (const float*)d_in[2];
    const float* b0 = (const float*)d_in[3];
    const float* W1 = (const float*)d_in[4];
    const float* R1 = (const float*)d_in[5];
    const float* b1 = (const float*)d_in[6];
    const float* W2 = (const float*)d_in[7];
    const float* R2 = (const float*)d_in[8];
    const float* b2 = (const float*)d_in[9];
    const float* Wd = (const float*)d_in[10];
    const float* bd = (const float*)d_in[11];
    float* out = (float*)d_out;

    // idempotent, called every launch (no static guards allowed)
    cudaFuncSetAttribute(k_lstm, cudaFuncAttributeMaxDynamicSharedMemorySize, LSTM_SMEM_BYTES);

    dim3 gemm_grid(NG / BN, (B_ * T_) / BM);

    // layer 0
    k_transpose_R<<<NG, U_>>>(R0);
    k_gemm_xw<<<gemm_grid, 256>>>(x, W0, b0, F_);
    k_lstm<<<B_ / 2, 512, LSTM_SMEM_BYTES>>>();
    // layer 1
    k_transpose_R<<<NG, U_>>>(R1);
    k_gemm_xw<<<gemm_grid, 256>>>(nullptr, W1, b1, U_);
    k_lstm<<<B_ / 2, 512, LSTM_SMEM_BYTES>>>();
    // layer 2
    k_transpose_R<<<NG, U_>>>(R2);
    k_gemm_xw<<<gemm_grid, 256>>>(nullptr, W2, b2, U_);
    k_lstm<<<B_ / 2, 512, LSTM_SMEM_BYTES>>>();
    // dense head
    k_dense<<<(B_ * OUT_ + 255) / 256, 256>>>(Wd, bd, out);
}

// round 2
// speedup vs baseline: 1.9544x; 1.9544x over previous
#include <cuda_runtime.h>
#include <math.h>

// Problem constants
#define U_    128          // LSTM units
#define NG    512          // 4*U (gate width)
#define T_    512          // timesteps
#define B_    256          // batch
#define F_    64           // input features
#define OUT_  6            // dense head
#define SMEM_COLS 416      // Rt columns resident in SMEM (rest via L2)
#define RPAD  132          // padded SMEM row stride (floats) -> conflict-free LDS.128

// ---------------- scratch (static device allocations only) ----------------
__device__ float g_xw[(size_t)B_ * T_ * NG];   // per-layer input projection [B*T, 512]
__device__ float g_h [(size_t)B_ * T_ * U_];   // per-layer hidden sequence  [B*T, 128]
__device__ float g_RT[NG * U_];                // transposed recurrent matrix [512,128]

// ---------------- R transpose: R[U,4U] -> RT[4U,U] ----------------
__global__ void k_transpose_R(const float* __restrict__ R) {
    int j = blockIdx.x;       // gate column 0..511
    int k = threadIdx.x;      // 0..127
    g_RT[j * U_ + k] = R[k * NG + j];
}

// ---------------- GEMM: g_xw[M,512] = A[M,K] @ W[K,512] + bias ----------------
#define BM 64
#define BN 64
#define BK 16
__global__ __launch_bounds__(256) void k_gemm_xw(const float* __restrict__ Ain,
                                                 const float* __restrict__ W,
                                                 const float* __restrict__ bias,
                                                 int K) {
    const float* A = Ain ? Ain : g_h;   // nullptr => previous layer's hidden sequence
    __shared__ float As[BK][BM];
    __shared__ float Bs[BK][BN + 4];
    const int brow = blockIdx.y * BM;
    const int bcol = blockIdx.x * BN;
    const int tid = threadIdx.x;
    const int tx = tid & 15, ty = tid >> 4;   // 16x16 thread grid, 4x4 micro tiles

    float acc[4][4] = {};
    for (int k0 = 0; k0 < K; k0 += BK) {
        #pragma unroll
        for (int i = tid; i < BK * BM; i += 256) {
            int m = i >> 4, k = i & 15;
            As[k][m] = A[(size_t)(brow + m) * K + (k0 + k)];
        }
        #pragma unroll
        for (int i = tid; i < BK * BN; i += 256) {
            int k = i >> 6, n = i & 63;
            Bs[k][n] = W[(size_t)(k0 + k) * NG + (bcol + n)];
        }
        __syncthreads();
        #pragma unroll
        for (int k = 0; k < BK; k++) {
            float a0 = As[k][ty * 4 + 0], a1 = As[k][ty * 4 + 1];
            float a2 = As[k][ty * 4 + 2], a3 = As[k][ty * 4 + 3];
            float4 bv = *reinterpret_cast<const float4*>(&Bs[k][tx * 4]);
            acc[0][0] = fmaf(a0, bv.x, acc[0][0]); acc[0][1] = fmaf(a0, bv.y, acc[0][1]);
            acc[0][2] = fmaf(a0, bv.z, acc[0][2]); acc[0][3] = fmaf(a0, bv.w, acc[0][3]);
            acc[1][0] = fmaf(a1, bv.x, acc[1][0]); acc[1][1] = fmaf(a1, bv.y, acc[1][1]);
            acc[1][2] = fmaf(a1, bv.z, acc[1][2]); acc[1][3] = fmaf(a1, bv.w, acc[1][3]);
            acc[2][0] = fmaf(a2, bv.x, acc[2][0]); acc[2][1] = fmaf(a2, bv.y, acc[2][1]);
            acc[2][2] = fmaf(a2, bv.z, acc[2][2]); acc[2][3] = fmaf(a2, bv.w, acc[2][3]);
            acc[3][0] = fmaf(a3, bv.x, acc[3][0]); acc[3][1] = fmaf(a3, bv.y, acc[3][1]);
            acc[3][2] = fmaf(a3, bv.z, acc[3][2]); acc[3][3] = fmaf(a3, bv.w, acc[3][3]);
        }
        __syncthreads();
    }
    #pragma unroll
    for (int i = 0; i < 4; i++) {
        size_t row = (size_t)(brow + ty * 4 + i);
        #pragma unroll
        for (int j = 0; j < 4; j++) {
            int col = bcol + tx * 4 + j;
            g_xw[row * NG + col] = acc[i][j] + bias[col];
        }
    }
}

// ---------------- LSTM scan: one CTA owns 2 batch rows for all T steps ----------------
// SMEM: Rt cols [0,416) resident, rows padded to 132 floats (516B) so that a warp's
// LDS.128 of rp[k] hits 8 distinct 128B segments -> conflict-free 4-wavefront floor.
// h loads are warp-uniform broadcasts (cheap). xw loads are software-pipelined.
#define LSTM_SMEM_FLOATS (SMEM_COLS * RPAD + 2 * U_ + 2 * U_ + 2 * NG)
#define LSTM_SMEM_BYTES  (LSTM_SMEM_FLOATS * 4)

__global__ __launch_bounds__(512) void k_lstm() {
    extern __shared__ float smem[];
    float* sR   = smem;                       // [SMEM_COLS][RPAD]
    float* sh   = sR + SMEM_COLS * RPAD;      // [2][128]
    float* sc   = sh + 2 * U_;                // [2][128]
    float* sact = sc + 2 * U_;                // [2][512] activated gates

    const int tid = threadIdx.x;              // gate column
    const int b0 = blockIdx.x * 2;

    // load R into padded SMEM layout
    for (int i = tid; i < SMEM_COLS * U_; i += 512) {
        int col = i >> 7, k = i & (U_ - 1);
        sR[col * RPAD + k] = g_RT[i];
    }
    if (tid < 2 * U_) { sh[tid] = 0.f; sc[tid] = 0.f; }
    __syncthreads();

    const float4* sh4 = reinterpret_cast<const float4*>(sh);
    const size_t xw0base = (size_t)b0 * T_ * NG;
    const size_t xw1base = (size_t)(b0 + 1) * T_ * NG;
    const bool in_smem = (tid < SMEM_COLS);
    const float4* rp = in_smem
        ? reinterpret_cast<const float4*>(sR + tid * RPAD)
        : reinterpret_cast<const float4*>(g_RT + tid * U_);

    // prefetch t=0 xw
    float pf0 = __ldcs(&g_xw[xw0base + tid]);
    float pf1 = __ldcs(&g_xw[xw1base + tid]);

    for (int t = 0; t < T_; t++) {
        float acc0 = pf0;
        float acc1 = pf1;
        // prefetch next step early (hides DRAM latency under the FMA loop)
        if (t + 1 < T_) {
            pf0 = __ldcs(&g_xw[xw0base + (size_t)(t + 1) * NG + tid]);
            pf1 = __ldcs(&g_xw[xw1base + (size_t)(t + 1) * NG + tid]);
        }

        #pragma unroll
        for (int k = 0; k < U_ / 4; k++) {
            float4 r  = rp[k];
            float4 h0 = sh4[k];              // broadcast
            float4 h1 = sh4[k + U_ / 4];     // broadcast
            acc0 = fmaf(h0.x, r.x, acc0); acc0 = fmaf(h0.y, r.y, acc0);
            acc0 = fmaf(h0.z, r.z, acc0); acc0 = fmaf(h0.w, r.w, acc0);
            acc1 = fmaf(h1.x, r.x, acc1); acc1 = fmaf(h1.y, r.y, acc1);
            acc1 = fmaf(h1.z, r.z, acc1); acc1 = fmaf(h1.w, r.w, acc1);
        }

        // gate activations (i,f,o: sigmoid; g: tanh). Warp-uniform branch (gate = tid>>7).
        float a0, a1;
        if ((tid >> 7) == 2) {
            a0 = tanhf(acc0); a1 = tanhf(acc1);
        } else {
            a0 = 1.f / (1.f + expf(-acc0));
            a1 = 1.f / (1.f + expf(-acc1));
        }
        sact[tid] = a0;
        sact[NG + tid] = a1;
        __syncthreads();

        if (tid < 2 * U_) {
            int m = tid >> 7, u = tid & (U_ - 1);
            const float* s = sact + m * NG;
            float iv = s[u], fv = s[U_ + u], gv = s[2 * U_ + u], ov = s[3 * U_ + u];
            float c = fmaf(fv, sc[tid], iv * gv);
            float h = ov * tanhf(c);
            sc[tid] = c;
            sh[tid] = h;
            g_h[((size_t)(b0 + m) * T_ + t) * U_ + u] = h;
        }
        __syncthreads();
    }
}

// ---------------- dense head: out[256,6] = h_last @ Wd + bd ----------------
__global__ void k_dense(const float* __restrict__ Wd, const float* __restrict__ bd,
                        float* __restrict__ out) {
    int idx = blockIdx.x * 256 + threadIdx.x;
    if (idx >= B_ * OUT_) return;
    int b = idx / OUT_, j = idx % OUT_;
    const float* hrow = &g_h[((size_t)b * T_ + (T_ - 1)) * U_];
    float s = bd[j];
    #pragma unroll
    for (int k = 0; k < U_; k++) s = fmaf(hrow[k], Wd[k * OUT_ + j], s);
    out[idx] = s;
}

// ---------------- launch ----------------
extern "C" void kernel_launch(void* const* d_in, const int* in_sizes, int n_in,
                              void* d_out, int out_size) {
    const float* x  = (const float*)d_in[0];
    const float* W0 = (const float*)d_in[1];
    const float* R0 = (const float*)d_in[2];
    const float* b0 = (const float*)d_in[3];
    const float* W1 = (const float*)d_in[4];
    const float* R1 = (const float*)d_in[5];
    const float* b1 = (const float*)d_in[6];
    const float* W2 = (const float*)d_in[7];
    const float* R2 = (const float*)d_in[8];
    const float* b2 = (const float*)d_in[9];
    const float* Wd = (const float*)d_in[10];
    const float* bd = (const float*)d_in[11];
    float* out = (float*)d_out;

    cudaFuncSetAttribute(k_lstm, cudaFuncAttributeMaxDynamicSharedMemorySize, LSTM_SMEM_BYTES);

    dim3 gemm_grid(NG / BN, (B_ * T_) / BM);

    // layer 0
    k_transpose_R<<<NG, U_>>>(R0);
    k_gemm_xw<<<gemm_grid, 256>>>(x, W0, b0, F_);
    k_lstm<<<B_ / 2, 512, LSTM_SMEM_BYTES>>>();
    // layer 1
    k_transpose_R<<<NG, U_>>>(R1);
    k_gemm_xw<<<gemm_grid, 256>>>(nullptr, W1, b1, U_);
    k_lstm<<<B_ / 2, 512, LSTM_SMEM_BYTES>>>();
    // layer 2
    k_transpose_R<<<NG, U_>>>(R2);
    k_gemm_xw<<<gemm_grid, 256>>>(nullptr, W2, b2, U_);
    k_lstm<<<B_ / 2, 512, LSTM_SMEM_BYTES>>>();
    // dense head
    k_dense<<<(B_ * OUT_ + 255) / 256, 256>>>(Wd, bd, out);
}

// round 3
// speedup vs baseline: 3.4196x; 1.7497x over previous
#include <cuda_runtime.h>
#include <math.h>

// Problem constants
#define U_    128          // LSTM units
#define NG    512          // 4*U (gate width)
#define T_    512          // timesteps
#define B_    256          // batch
#define F_    64           // input features
#define OUT_  6            // dense head

// R split per gate column: 68 k-values in SMEM, 60 in registers
#define KSM   68           // SMEM-resident k-values (stride 272B == 16 mod 128 -> conflict-free)
#define KRG   60           // register-resident k-values
#define NQ_SM (KSM / 4)    // 17 double2 per column in SMEM
#define NQ_RG (KRG / 4)    // 15 double2 per column in registers

typedef unsigned long long ull;

// packed f32x2 FMA: acc.lo += a.lo*b.lo ; acc.hi += a.hi*b.hi
#define FMA2(acc, a, b) \
    asm("fma.rn.f32x2 %0, %1, %2, %0;" : "+l"(acc) \
        : "l"(__double_as_longlong(a)), "l"(__double_as_longlong(b)))

__device__ __forceinline__ float unpack_sum(ull v) {
    return __int_as_float((int)(v & 0xffffffffull)) + __int_as_float((int)(v >> 32));
}

// ---------------- scratch ----------------
__device__ float g_xw[(size_t)B_ * T_ * NG];   // input projection [B*T, 512]
__device__ float g_h [(size_t)B_ * T_ * U_];   // hidden sequence  [B*T, 128]
__device__ float g_RT[NG * U_];                // transposed recurrent matrix [512,128]

// ---------------- R transpose: R[U,4U] -> RT[4U,U] ----------------
__global__ void k_transpose_R(const float* __restrict__ R) {
    int j = blockIdx.x;
    int k = threadIdx.x;
    g_RT[j * U_ + k] = R[k * NG + j];
}

// ---------------- GEMM: g_xw[M,512] = A[M,K] @ W[K,512] + bias ----------------
#define BM 64
#define BN 64
#define BK 16
__global__ __launch_bounds__(256) void k_gemm_xw(const float* __restrict__ Ain,
                                                 const float* __restrict__ W,
                                                 const float* __restrict__ bias,
                                                 int K) {
    const float* A = Ain ? Ain : g_h;
    __shared__ float As[BK][BM];
    __shared__ float Bs[BK][BN + 4];
    const int brow = blockIdx.y * BM;
    const int bcol = blockIdx.x * BN;
    const int tid = threadIdx.x;
    const int tx = tid & 15, ty = tid >> 4;

    float acc[4][4] = {};
    for (int k0 = 0; k0 < K; k0 += BK) {
        #pragma unroll
        for (int i = tid; i < BK * BM; i += 256) {
            int m = i >> 4, k = i & 15;
            As[k][m] = A[(size_t)(brow + m) * K + (k0 + k)];
        }
        #pragma unroll
        for (int i = tid; i < BK * BN; i += 256) {
            int k = i >> 6, n = i & 63;
            Bs[k][n] = W[(size_t)(k0 + k) * NG + (bcol + n)];
        }
        __syncthreads();
        #pragma unroll
        for (int k = 0; k < BK; k++) {
            float a0 = As[k][ty * 4 + 0], a1 = As[k][ty * 4 + 1];
            float a2 = As[k][ty * 4 + 2], a3 = As[k][ty * 4 + 3];
            float4 bv = *reinterpret_cast<const float4*>(&Bs[k][tx * 4]);
            acc[0][0] = fmaf(a0, bv.x, acc[0][0]); acc[0][1] = fmaf(a0, bv.y, acc[0][1]);
            acc[0][2] = fmaf(a0, bv.z, acc[0][2]); acc[0][3] = fmaf(a0, bv.w, acc[0][3]);
            acc[1][0] = fmaf(a1, bv.x, acc[1][0]); acc[1][1] = fmaf(a1, bv.y, acc[1][1]);
            acc[1][2] = fmaf(a1, bv.z, acc[1][2]); acc[1][3] = fmaf(a1, bv.w, acc[1][3]);
            acc[2][0] = fmaf(a2, bv.x, acc[2][0]); acc[2][1] = fmaf(a2, bv.y, acc[2][1]);
            acc[2][2] = fmaf(a2, bv.z, acc[2][2]); acc[2][3] = fmaf(a2, bv.w, acc[2][3]);
            acc[3][0] = fmaf(a3, bv.x, acc[3][0]); acc[3][1] = fmaf(a3, bv.y, acc[3][1]);
            acc[3][2] = fmaf(a3, bv.z, acc[3][2]); acc[3][3] = fmaf(a3, bv.w, acc[3][3]);
        }
        __syncthreads();
    }
    #pragma unroll
    for (int i = 0; i < 4; i++) {
        size_t row = (size_t)(brow + ty * 4 + i);
        #pragma unroll
        for (int j = 0; j < 4; j++) {
            int col = bcol + tx * 4 + j;
            g_xw[row * NG + col] = acc[i][j] + bias[col];
        }
    }
}

// ---------------- LSTM scan: one CTA owns 2 batch rows for all T steps ----------------
// R split: 68 k in SMEM (conflict-free layout), 60 k in registers (loaded once).
// No global loads of R in the step loop -> no straggler warps.
#define LSTM_SMEM_FLOATS (NG * KSM + 2 * U_ + 2 * U_ + 2 * NG)
#define LSTM_SMEM_BYTES  (LSTM_SMEM_FLOATS * 4)

__global__ __launch_bounds__(512) void k_lstm() {
    extern __shared__ float smem[];
    float* sR   = smem;                       // [512][KSM]
    float* sh   = sR + NG * KSM;              // [2][128]
    float* sc   = sh + 2 * U_;                // [2][128]
    float* sact = sc + 2 * U_;                // [2][512]

    const int tid = threadIdx.x;              // gate column
    const int b0 = blockIdx.x * 2;

    // SMEM R: first KSM k-values of each column
    for (int i = tid; i < NG * KSM; i += 512) {
        int col = i / KSM, k = i - col * KSM;
        sR[i] = g_RT[col * U_ + k];
    }
    // Register R: remaining KRG k-values of THIS thread's column (packed f32 pairs)
    double rr[NQ_RG * 2];
    {
        const double2* rg = reinterpret_cast<const double2*>(g_RT + tid * U_ + KSM);
        #pragma unroll
        for (int q = 0; q < NQ_RG; q++) {
            double2 v = rg[q];
            rr[2 * q] = v.x; rr[2 * q + 1] = v.y;
        }
    }
    if (tid < 2 * U_) { sh[tid] = 0.f; sc[tid] = 0.f; }
    __syncthreads();

    const double2* rs  = reinterpret_cast<const double2*>(sR + tid * KSM);
    const double2* h0p = reinterpret_cast<const double2*>(sh);
    const double2* h1p = reinterpret_cast<const double2*>(sh + U_);
    const size_t xw0base = (size_t)b0 * T_ * NG;
    const size_t xw1base = (size_t)(b0 + 1) * T_ * NG;

    float pf0 = __ldcs(&g_xw[xw0base + tid]);
    float pf1 = __ldcs(&g_xw[xw1base + tid]);

    for (int t = 0; t < T_; t++) {
        ull acc0 = (ull)__float_as_uint(pf0);   // lo = xw, hi = 0
        ull acc1 = (ull)__float_as_uint(pf1);
        if (t + 1 < T_) {
            pf0 = __ldcs(&g_xw[xw0base + (size_t)(t + 1) * NG + tid]);
            pf1 = __ldcs(&g_xw[xw1base + (size_t)(t + 1) * NG + tid]);
        }

        // SMEM-resident R: k in [0, KSM)
        #pragma unroll
        for (int q = 0; q < NQ_SM; q++) {
            double2 r = rs[q];
            double2 a = h0p[q];
            double2 b = h1p[q];
            FMA2(acc0, r.x, a.x); FMA2(acc0, r.y, a.y);
            FMA2(acc1, r.x, b.x); FMA2(acc1, r.y, b.y);
        }
        // Register-resident R: k in [KSM, 128)
        #pragma unroll
        for (int q = 0; q < NQ_RG; q++) {
            double2 a = h0p[NQ_SM + q];
            double2 b = h1p[NQ_SM + q];
            FMA2(acc0, rr[2 * q], a.x); FMA2(acc0, rr[2 * q + 1], a.y);
            FMA2(acc1, rr[2 * q], b.x); FMA2(acc1, rr[2 * q + 1], b.y);
        }

        float z0 = unpack_sum(acc0);
        float z1 = unpack_sum(acc1);

        float a0, a1;
        if ((tid >> 7) == 2) {                 // g gate: tanh
            a0 = tanhf(z0); a1 = tanhf(z1);
        } else {                               // i,f,o: sigmoid (fast exp)
            a0 = 1.f / (1.f + __expf(-z0));
            a1 = 1.f / (1.f + __expf(-z1));
        }
        sact[tid] = a0;
        sact[NG + tid] = a1;
        __syncthreads();

        if (tid < 2 * U_) {
            int m = tid >> 7, u = tid & (U_ - 1);
            const float* s = sact + m * NG;
            float iv = s[u], fv = s[U_ + u], gv = s[2 * U_ + u], ov = s[3 * U_ + u];
            float c = fmaf(fv, sc[tid], iv * gv);
            float h = ov * tanhf(c);
            sc[tid] = c;
            sh[tid] = h;
            g_h[((size_t)(b0 + m) * T_ + t) * U_ + u] = h;
        }
        __syncthreads();
    }
}

// ---------------- dense head ----------------
__global__ void k_dense(const float* __restrict__ Wd, const float* __restrict__ bd,
                        float* __restrict__ out) {
    int idx = blockIdx.x * 256 + threadIdx.x;
    if (idx >= B_ * OUT_) return;
    int b = idx / OUT_, j = idx % OUT_;
    const float* hrow = &g_h[((size_t)b * T_ + (T_ - 1)) * U_];
    float s = bd[j];
    #pragma unroll
    for (int k = 0; k < U_; k++) s = fmaf(hrow[k], Wd[k * OUT_ + j], s);
    out[idx] = s;
}

// ---------------- launch ----------------
extern "C" void kernel_launch(void* const* d_in, const int* in_sizes, int n_in,
                              void* d_out, int out_size) {
    const float* x  = (const float*)d_in[0];
    const float* W0 = (const float*)d_in[1];
    const float* R0 = (const float*)d_in[2];
    const float* b0 = (const float*)d_in[3];
    const float* W1 = (const float*)d_in[4];
    const float* R1 = (const float*)d_in[5];
    const float* b1 = (const float*)d_in[6];
    const float* W2 = (const float*)d_in[7];
    const float* R2 = (const float*)d_in[8];
    const float* b2 = (const float*)d_in[9];
    const float* Wd = (const float*)d_in[10];
    const float* bd = (const float*)d_in[11];
    float* out = (float*)d_out;

    cudaFuncSetAttribute(k_lstm, cudaFuncAttributeMaxDynamicSharedMemorySize, LSTM_SMEM_BYTES);

    dim3 gemm_grid(NG / BN, (B_ * T_) / BM);

    k_transpose_R<<<NG, U_>>>(R0);
    k_gemm_xw<<<gemm_grid, 256>>>(x, W0, b0, F_);
    k_lstm<<<B_ / 2, 512, LSTM_SMEM_BYTES>>>();

    k_transpose_R<<<NG, U_>>>(R1);
    k_gemm_xw<<<gemm_grid, 256>>>(nullptr, W1, b1, U_);
    k_lstm<<<B_ / 2, 512, LSTM_SMEM_BYTES>>>();

    k_transpose_R<<<NG, U_>>>(R2);
    k_gemm_xw<<<gemm_grid, 256>>>(nullptr, W2, b2, U_);
    k_lstm<<<B_ / 2, 512, LSTM_SMEM_BYTES>>>();

    k_dense<<<(B_ * OUT_ + 255) / 256, 256>>>(Wd, bd, out);
}

// round 4
// speedup vs baseline: 4.0186x; 1.1752x over previous
#include <cuda_runtime.h>
#include <math.h>

// Problem constants
#define U_    128          // LSTM units
#define NG    512          // 4*U (gate width)
#define T_    512          // timesteps
#define B_    256          // batch
#define F_    64           // input features
#define OUT_  6            // dense head

// R split per gate column: 68 k-values in SMEM, 60 in registers
#define KSM   68
#define KRG   60
#define NQ_SM (KSM / 4)
#define NQ_RG (KRG / 4)

typedef unsigned long long ull;

// packed f32x2 FMA on raw 64-bit pairs
#define FMA2U(acc, a, b) \
    asm("fma.rn.f32x2 %0, %1, %2, %0;" : "+l"(acc) : "l"(a), "l"(b))
// packed f32x2 FMA taking doubles (bit-reinterpreted pairs)
#define FMA2(acc, a, b) \
    asm("fma.rn.f32x2 %0, %1, %2, %0;" : "+l"(acc) \
        : "l"(__double_as_longlong(a)), "l"(__double_as_longlong(b)))

__device__ __forceinline__ ull dup2(float x) {
    ull r;
    asm("mov.b64 %0, {%1, %1};" : "=l"(r) : "f"(x));
    return r;
}
__device__ __forceinline__ float lo32(ull v) { return __int_as_float((int)(v & 0xffffffffull)); }
__device__ __forceinline__ float hi32(ull v) { return __int_as_float((int)(v >> 32)); }
__device__ __forceinline__ float unpack_sum(ull v) { return lo32(v) + hi32(v); }

// ---------------- scratch ----------------
__device__ float g_xw[(size_t)B_ * T_ * NG];   // input projection [B*T, 512]
__device__ float g_h [(size_t)B_ * T_ * U_];   // hidden sequence  [B*T, 128]
__device__ float g_RT[NG * U_];                // transposed recurrent matrix [512,128]

// ---------------- R transpose: R[U,4U] -> RT[4U,U] ----------------
__global__ void k_transpose_R(const float* __restrict__ R) {
    int j = blockIdx.x;
    int k = threadIdx.x;
    g_RT[j * U_ + k] = R[k * NG + j];
}

// ---------------- GEMM: g_xw[M,512] = A[M,K] @ W[K,512] + bias ----------------
// 128x128 tile, BK=8, 256 threads, 8x8 micro-tile, packed f32x2 accumulators.
#define GBM 128
#define GBN 128
#define GBK 8
#define GPAD 4
__global__ __launch_bounds__(256) void k_gemm_xw(const float* __restrict__ Ain,
                                                 const float* __restrict__ W,
                                                 const float* __restrict__ bias,
                                                 int K) {
    const float* A = Ain ? Ain : g_h;
    __shared__ float As[GBK][GBM + GPAD];
    __shared__ float Bs[GBK][GBN + GPAD];
    const int brow = blockIdx.y * GBM;
    const int bcol = blockIdx.x * GBN;
    const int tid = threadIdx.x;
    const int tx = tid & 15;          // n-block (8 cols)
    const int ty = tid >> 4;          // m-block (8 rows)

    // A-load mapping: one float4 along k per thread
    const int a_m  = tid >> 1;               // 0..127
    const int a_kq = (tid & 1) * 4;          // 0 or 4
    // B-load mapping: one float4 along n per thread
    const int b_k  = tid >> 5;                // 0..7
    const int b_n  = (tid & 31) * 4;          // 0..124

    ull acc2[8][4];
    #pragma unroll
    for (int i = 0; i < 8; i++)
        #pragma unroll
        for (int j = 0; j < 4; j++) acc2[i][j] = 0ull;

    for (int k0 = 0; k0 < K; k0 += GBK) {
        float4 av = *reinterpret_cast<const float4*>(&A[(size_t)(brow + a_m) * K + (k0 + a_kq)]);
        As[a_kq + 0][a_m] = av.x;
        As[a_kq + 1][a_m] = av.y;
        As[a_kq + 2][a_m] = av.z;
        As[a_kq + 3][a_m] = av.w;
        *reinterpret_cast<float4*>(&Bs[b_k][b_n]) =
            *reinterpret_cast<const float4*>(&W[(size_t)(k0 + b_k) * NG + (bcol + b_n)]);
        __syncthreads();

        #pragma unroll
        for (int k = 0; k < GBK; k++) {
            float4 a0 = *reinterpret_cast<const float4*>(&As[k][ty * 8]);
            float4 a1 = *reinterpret_cast<const float4*>(&As[k][ty * 8 + 4]);
            ulonglong2 bv0 = *reinterpret_cast<const ulonglong2*>(&Bs[k][tx * 8]);
            ulonglong2 bv1 = *reinterpret_cast<const ulonglong2*>(&Bs[k][tx * 8 + 4]);
            ull ad;
            ad = dup2(a0.x);
            FMA2U(acc2[0][0], ad, bv0.x); FMA2U(acc2[0][1], ad, bv0.y);
            FMA2U(acc2[0][2], ad, bv1.x); FMA2U(acc2[0][3], ad, bv1.y);
            ad = dup2(a0.y);
            FMA2U(acc2[1][0], ad, bv0.x); FMA2U(acc2[1][1], ad, bv0.y);
            FMA2U(acc2[1][2], ad, bv1.x); FMA2U(acc2[1][3], ad, bv1.y);
            ad = dup2(a0.z);
            FMA2U(acc2[2][0], ad, bv0.x); FMA2U(acc2[2][1], ad, bv0.y);
            FMA2U(acc2[2][2], ad, bv1.x); FMA2U(acc2[2][3], ad, bv1.y);
            ad = dup2(a0.w);
            FMA2U(acc2[3][0], ad, bv0.x); FMA2U(acc2[3][1], ad, bv0.y);
            FMA2U(acc2[3][2], ad, bv1.x); FMA2U(acc2[3][3], ad, bv1.y);
            ad = dup2(a1.x);
            FMA2U(acc2[4][0], ad, bv0.x); FMA2U(acc2[4][1], ad, bv0.y);
            FMA2U(acc2[4][2], ad, bv1.x); FMA2U(acc2[4][3], ad, bv1.y);
            ad = dup2(a1.y);
            FMA2U(acc2[5][0], ad, bv0.x); FMA2U(acc2[5][1], ad, bv0.y);
            FMA2U(acc2[5][2], ad, bv1.x); FMA2U(acc2[5][3], ad, bv1.y);
            ad = dup2(a1.z);
            FMA2U(acc2[6][0], ad, bv0.x); FMA2U(acc2[6][1], ad, bv0.y);
            FMA2U(acc2[6][2], ad, bv1.x); FMA2U(acc2[6][3], ad, bv1.y);
            ad = dup2(a1.w);
            FMA2U(acc2[7][0], ad, bv0.x); FMA2U(acc2[7][1], ad, bv0.y);
            FMA2U(acc2[7][2], ad, bv1.x); FMA2U(acc2[7][3], ad, bv1.y);
        }
        __syncthreads();
    }

    // epilogue: unpack, add bias, store 2x float4 per row
    const int col0 = bcol + tx * 8;
    float bb[8];
    #pragma unroll
    for (int j = 0; j < 8; j++) bb[j] = bias[col0 + j];
    #pragma unroll
    for (int i = 0; i < 8; i++) {
        size_t row = (size_t)(brow + ty * 8 + i);
        float4 o0, o1;
        o0.x = lo32(acc2[i][0]) + bb[0]; o0.y = hi32(acc2[i][0]) + bb[1];
        o0.z = lo32(acc2[i][1]) + bb[2]; o0.w = hi32(acc2[i][1]) + bb[3];
        o1.x = lo32(acc2[i][2]) + bb[4]; o1.y = hi32(acc2[i][2]) + bb[5];
        o1.z = lo32(acc2[i][3]) + bb[6]; o1.w = hi32(acc2[i][3]) + bb[7];
        *reinterpret_cast<float4*>(&g_xw[row * NG + col0])     = o0;
        *reinterpret_cast<float4*>(&g_xw[row * NG + col0 + 4]) = o1;
    }
}

// ---------------- LSTM scan (unchanged from round 3) ----------------
#define LSTM_SMEM_FLOATS (NG * KSM + 2 * U_ + 2 * U_ + 2 * NG)
#define LSTM_SMEM_BYTES  (LSTM_SMEM_FLOATS * 4)

__global__ __launch_bounds__(512) void k_lstm() {
    extern __shared__ float smem[];
    float* sR   = smem;                       // [512][KSM]
    float* sh   = sR + NG * KSM;              // [2][128]
    float* sc   = sh + 2 * U_;                // [2][128]
    float* sact = sc + 2 * U_;                // [2][512]

    const int tid = threadIdx.x;
    const int b0 = blockIdx.x * 2;

    for (int i = tid; i < NG * KSM; i += 512) {
        int col = i / KSM, k = i - col * KSM;
        sR[i] = g_RT[col * U_ + k];
    }
    double rr[NQ_RG * 2];
    {
        const double2* rg = reinterpret_cast<const double2*>(g_RT + tid * U_ + KSM);
        #pragma unroll
        for (int q = 0; q < NQ_RG; q++) {
            double2 v = rg[q];
            rr[2 * q] = v.x; rr[2 * q + 1] = v.y;
        }
    }
    if (tid < 2 * U_) { sh[tid] = 0.f; sc[tid] = 0.f; }
    __syncthreads();

    const double2* rs  = reinterpret_cast<const double2*>(sR + tid * KSM);
    const double2* h0p = reinterpret_cast<const double2*>(sh);
    const double2* h1p = reinterpret_cast<const double2*>(sh + U_);
    const size_t xw0base = (size_t)b0 * T_ * NG;
    const size_t xw1base = (size_t)(b0 + 1) * T_ * NG;

    float pf0 = __ldcs(&g_xw[xw0base + tid]);
    float pf1 = __ldcs(&g_xw[xw1base + tid]);

    for (int t = 0; t < T_; t++) {
        ull acc0 = (ull)__float_as_uint(pf0);
        ull acc1 = (ull)__float_as_uint(pf1);
        if (t + 1 < T_) {
            pf0 = __ldcs(&g_xw[xw0base + (size_t)(t + 1) * NG + tid]);
            pf1 = __ldcs(&g_xw[xw1base + (size_t)(t + 1) * NG + tid]);
        }

        #pragma unroll
        for (int q = 0; q < NQ_SM; q++) {
            double2 r = rs[q];
            double2 a = h0p[q];
            double2 b = h1p[q];
            FMA2(acc0, r.x, a.x); FMA2(acc0, r.y, a.y);
            FMA2(acc1, r.x, b.x); FMA2(acc1, r.y, b.y);
        }
        #pragma unroll
        for (int q = 0; q < NQ_RG; q++) {
            double2 a = h0p[NQ_SM + q];
            double2 b = h1p[NQ_SM + q];
            FMA2(acc0, rr[2 * q], a.x); FMA2(acc0, rr[2 * q + 1], a.y);
            FMA2(acc1, rr[2 * q], b.x); FMA2(acc1, rr[2 * q + 1], b.y);
        }

        float z0 = unpack_sum(acc0);
        float z1 = unpack_sum(acc1);

        float a0, a1;
        if ((tid >> 7) == 2) {
            a0 = tanhf(z0); a1 = tanhf(z1);
        } else {
            a0 = 1.f / (1.f + __expf(-z0));
            a1 = 1.f / (1.f + __expf(-z1));
        }
        sact[tid] = a0;
        sact[NG + tid] = a1;
        __syncthreads();

        if (tid < 2 * U_) {
            int m = tid >> 7, u = tid & (U_ - 1);
            const float* s = sact + m * NG;
            float iv = s[u], fv = s[U_ + u], gv = s[2 * U_ + u], ov = s[3 * U_ + u];
            float c = fmaf(fv, sc[tid], iv * gv);
            float h = ov * tanhf(c);
            sc[tid] = c;
            sh[tid] = h;
            g_h[((size_t)(b0 + m) * T_ + t) * U_ + u] = h;
        }
        __syncthreads();
    }
}

// ---------------- dense head ----------------
__global__ void k_dense(const float* __restrict__ Wd, const float* __restrict__ bd,
                        float* __restrict__ out) {
    int idx = blockIdx.x * 256 + threadIdx.x;
    if (idx >= B_ * OUT_) return;
    int b = idx / OUT_, j = idx % OUT_;
    const float* hrow = &g_h[((size_t)b * T_ + (T_ - 1)) * U_];
    float s = bd[j];
    #pragma unroll
    for (int k = 0; k < U_; k++) s = fmaf(hrow[k], Wd[k * OUT_ + j], s);
    out[idx] = s;
}

// ---------------- launch ----------------
extern "C" void kernel_launch(void* const* d_in, const int* in_sizes, int n_in,
                              void* d_out, int out_size) {
    const float* x  = (const float*)d_in[0];
    const float* W0 = (const float*)d_in[1];
    const float* R0 = (const float*)d_in[2];
    const float* b0 = (const float*)d_in[3];
    const float* W1 = (const float*)d_in[4];
    const float* R1 = (const float*)d_in[5];
    const float* b1 = (const float*)d_in[6];
    const float* W2 = (const float*)d_in[7];
    const float* R2 = (const float*)d_in[8];
    const float* b2 = (const float*)d_in[9];
    const float* Wd = (const float*)d_in[10];
    const float* bd = (const float*)d_in[11];
    float* out = (float*)d_out;

    cudaFuncSetAttribute(k_lstm, cudaFuncAttributeMaxDynamicSharedMemorySize, LSTM_SMEM_BYTES);

    dim3 gemm_grid(NG / GBN, (B_ * T_) / GBM);

    k_transpose_R<<<NG, U_>>>(R0);
    k_gemm_xw<<<gemm_grid, 256>>>(x, W0, b0, F_);
    k_lstm<<<B_ / 2, 512, LSTM_SMEM_BYTES>>>();

    k_transpose_R<<<NG, U_>>>(R1);
    k_gemm_xw<<<gemm_grid, 256>>>(nullptr, W1, b1, U_);
    k_lstm<<<B_ / 2, 512, LSTM_SMEM_BYTES>>>();

    k_transpose_R<<<NG, U_>>>(R2);
    k_gemm_xw<<<gemm_grid, 256>>>(nullptr, W2, b2, U_);
    k_lstm<<<B_ / 2, 512, LSTM_SMEM_BYTES>>>();

    k_dense<<<(B_ * OUT_ + 255) / 256, 256>>>(Wd, bd, out);
}

// round 5
// speedup vs baseline: 4.3789x; 1.0897x over previous
#include <cuda_runtime.h>
#include <math.h>

// Problem constants
#define U_    128          // LSTM units
#define NG    512          // 4*U (gate width)
#define T_    512          // timesteps
#define B_    256          // batch
#define F_    64           // input features
#define OUT_  6            // dense head

// R split per gate column: 52 k-values in SMEM, 76 in registers
// stride 52*4=208B; 208 mod 128 = 80, gcd(80,128)=16 -> conflict-free LDS.128
#define KSM   52
#define KRG   76
#define NQ_SM (KSM / 4)    // 13
#define NQ_RG (KRG / 4)    // 19

typedef unsigned long long ull;

#define FMA2U(acc, a, b) \
    asm("fma.rn.f32x2 %0, %1, %2, %0;" : "+l"(acc) : "l"(a), "l"(b))
#define FMA2(acc, a, b) \
    asm("fma.rn.f32x2 %0, %1, %2, %0;" : "+l"(acc) \
        : "l"(__double_as_longlong(a)), "l"(__double_as_longlong(b)))

__device__ __forceinline__ ull dup2(float x) {
    ull r;
    asm("mov.b64 %0, {%1, %1};" : "=l"(r) : "f"(x));
    return r;
}
__device__ __forceinline__ float lo32(ull v) { return __int_as_float((int)(v & 0xffffffffull)); }
__device__ __forceinline__ float hi32(ull v) { return __int_as_float((int)(v >> 32)); }
__device__ __forceinline__ float unpack_sum(ull v) { return lo32(v) + hi32(v); }

// fast activations: ex2.approx + rcp.approx, no IEEE div, no libm branches
__device__ __forceinline__ float fast_sigmoid(float x) {
    return __fdividef(1.f, 1.f + __expf(-x));
}
__device__ __forceinline__ float fast_tanh(float x) {
    float e = __expf(fminf(-2.f * x, 80.f));   // clamp avoids inf/inf NaN
    return __fdividef(1.f - e, 1.f + e);
}

// ---------------- scratch ----------------
__device__ float g_xw[(size_t)B_ * T_ * NG];   // input projection [B*T, 512]
__device__ float g_h [(size_t)B_ * T_ * U_];   // hidden sequence  [B*T, 128]
__device__ float g_RT[NG * U_];                // transposed recurrent matrix [512,128]

// ---------------- R transpose ----------------
__global__ void k_transpose_R(const float* __restrict__ R) {
    int j = blockIdx.x;
    int k = threadIdx.x;
    g_RT[j * U_ + k] = R[k * NG + j];
}

// ---------------- GEMM: g_xw[M,512] = A[M,K] @ W[K,512] + bias (unchanged R4) ----------------
#define GBM 128
#define GBN 128
#define GBK 8
#define GPAD 4
__global__ __launch_bounds__(256) void k_gemm_xw(const float* __restrict__ Ain,
                                                 const float* __restrict__ W,
                                                 const float* __restrict__ bias,
                                                 int K) {
    const float* A = Ain ? Ain : g_h;
    __shared__ float As[GBK][GBM + GPAD];
    __shared__ float Bs[GBK][GBN + GPAD];
    const int brow = blockIdx.y * GBM;
    const int bcol = blockIdx.x * GBN;
    const int tid = threadIdx.x;
    const int tx = tid & 15;
    const int ty = tid >> 4;

    const int a_m  = tid >> 1;
    const int a_kq = (tid & 1) * 4;
    const int b_k  = tid >> 5;
    const int b_n  = (tid & 31) * 4;

    ull acc2[8][4];
    #pragma unroll
    for (int i = 0; i < 8; i++)
        #pragma unroll
        for (int j = 0; j < 4; j++) acc2[i][j] = 0ull;

    for (int k0 = 0; k0 < K; k0 += GBK) {
        float4 av = *reinterpret_cast<const float4*>(&A[(size_t)(brow + a_m) * K + (k0 + a_kq)]);
        As[a_kq + 0][a_m] = av.x;
        As[a_kq + 1][a_m] = av.y;
        As[a_kq + 2][a_m] = av.z;
        As[a_kq + 3][a_m] = av.w;
        *reinterpret_cast<float4*>(&Bs[b_k][b_n]) =
            *reinterpret_cast<const float4*>(&W[(size_t)(k0 + b_k) * NG + (bcol + b_n)]);
        __syncthreads();

        #pragma unroll
        for (int k = 0; k < GBK; k++) {
            float4 a0 = *reinterpret_cast<const float4*>(&As[k][ty * 8]);
            float4 a1 = *reinterpret_cast<const float4*>(&As[k][ty * 8 + 4]);
            ulonglong2 bv0 = *reinterpret_cast<const ulonglong2*>(&Bs[k][tx * 8]);
            ulonglong2 bv1 = *reinterpret_cast<const ulonglong2*>(&Bs[k][tx * 8 + 4]);
            ull ad;
            ad = dup2(a0.x);
            FMA2U(acc2[0][0], ad, bv0.x); FMA2U(acc2[0][1], ad, bv0.y);
            FMA2U(acc2[0][2], ad, bv1.x); FMA2U(acc2[0][3], ad, bv1.y);
            ad = dup2(a0.y);
            FMA2U(acc2[1][0], ad, bv0.x); FMA2U(acc2[1][1], ad, bv0.y);
            FMA2U(acc2[1][2], ad, bv1.x); FMA2U(acc2[1][3], ad, bv1.y);
            ad = dup2(a0.z);
            FMA2U(acc2[2][0], ad, bv0.x); FMA2U(acc2[2][1], ad, bv0.y);
            FMA2U(acc2[2][2], ad, bv1.x); FMA2U(acc2[2][3], ad, bv1.y);
            ad = dup2(a0.w);
            FMA2U(acc2[3][0], ad, bv0.x); FMA2U(acc2[3][1], ad, bv0.y);
            FMA2U(acc2[3][2], ad, bv1.x); FMA2U(acc2[3][3], ad, bv1.y);
            ad = dup2(a1.x);
            FMA2U(acc2[4][0], ad, bv0.x); FMA2U(acc2[4][1], ad, bv0.y);
            FMA2U(acc2[4][2], ad, bv1.x); FMA2U(acc2[4][3], ad, bv1.y);
            ad = dup2(a1.y);
            FMA2U(acc2[5][0], ad, bv0.x); FMA2U(acc2[5][1], ad, bv0.y);
            FMA2U(acc2[5][2], ad, bv1.x); FMA2U(acc2[5][3], ad, bv1.y);
            ad = dup2(a1.z);
            FMA2U(acc2[6][0], ad, bv0.x); FMA2U(acc2[6][1], ad, bv0.y);
            FMA2U(acc2[6][2], ad, bv1.x); FMA2U(acc2[6][3], ad, bv1.y);
            ad = dup2(a1.w);
            FMA2U(acc2[7][0], ad, bv0.x); FMA2U(acc2[7][1], ad, bv0.y);
            FMA2U(acc2[7][2], ad, bv1.x); FMA2U(acc2[7][3], ad, bv1.y);
        }
        __syncthreads();
    }

    const int col0 = bcol + tx * 8;
    float bb[8];
    #pragma unroll
    for (int j = 0; j < 8; j++) bb[j] = bias[col0 + j];
    #pragma unroll
    for (int i = 0; i < 8; i++) {
        size_t row = (size_t)(brow + ty * 8 + i);
        float4 o0, o1;
        o0.x = lo32(acc2[i][0]) + bb[0]; o0.y = hi32(acc2[i][0]) + bb[1];
        o0.z = lo32(acc2[i][1]) + bb[2]; o0.w = hi32(acc2[i][1]) + bb[3];
        o1.x = lo32(acc2[i][2]) + bb[4]; o1.y = hi32(acc2[i][2]) + bb[5];
        o1.z = lo32(acc2[i][3]) + bb[6]; o1.w = hi32(acc2[i][3]) + bb[7];
        *reinterpret_cast<float4*>(&g_xw[row * NG + col0])     = o0;
        *reinterpret_cast<float4*>(&g_xw[row * NG + col0 + 4]) = o1;
    }
}

// ---------------- LSTM scan ----------------
#define LSTM_SMEM_FLOATS (NG * KSM + 2 * U_ + 2 * U_ + 2 * NG)
#define LSTM_SMEM_BYTES  (LSTM_SMEM_FLOATS * 4)

__global__ __launch_bounds__(512) void k_lstm() {
    extern __shared__ float smem[];
    float* sR   = smem;                       // [512][KSM]
    float* sh   = sR + NG * KSM;              // [2][128]
    float* sc   = sh + 2 * U_;                // [2][128]
    float* sact = sc + 2 * U_;                // [2][512]

    const int tid = threadIdx.x;
    const int b0 = blockIdx.x * 2;

    for (int i = tid; i < NG * KSM; i += 512) {
        int col = i / KSM, k = i - col * KSM;
        sR[i] = g_RT[col * U_ + k];
    }
    double rr[NQ_RG * 2];
    {
        const double2* rg = reinterpret_cast<const double2*>(g_RT + tid * U_ + KSM);
        #pragma unroll
        for (int q = 0; q < NQ_RG; q++) {
            double2 v = rg[q];
            rr[2 * q] = v.x; rr[2 * q + 1] = v.y;
        }
    }
    if (tid < 2 * U_) { sh[tid] = 0.f; sc[tid] = 0.f; }
    __syncthreads();

    const double2* rs  = reinterpret_cast<const double2*>(sR + tid * KSM);
    const double2* h0p = reinterpret_cast<const double2*>(sh);
    const double2* h1p = reinterpret_cast<const double2*>(sh + U_);
    const size_t xw0base = (size_t)b0 * T_ * NG;
    const size_t xw1base = (size_t)(b0 + 1) * T_ * NG;

    float pf0 = __ldcs(&g_xw[xw0base + tid]);
    float pf1 = __ldcs(&g_xw[xw1base + tid]);

    for (int t = 0; t < T_; t++) {
        // dual chains per row for FMA latency tolerance
        ull acc0 = (ull)__float_as_uint(pf0), acc0b = 0ull;
        ull acc1 = (ull)__float_as_uint(pf1), acc1b = 0ull;
        if (t + 1 < T_) {
            pf0 = __ldcs(&g_xw[xw0base + (size_t)(t + 1) * NG + tid]);
            pf1 = __ldcs(&g_xw[xw1base + (size_t)(t + 1) * NG + tid]);
        }

        #pragma unroll
        for (int q = 0; q < NQ_SM; q++) {
            double2 r = rs[q];
            double2 a = h0p[q];
            double2 b = h1p[q];
            FMA2(acc0, r.x, a.x); FMA2(acc0b, r.y, a.y);
            FMA2(acc1, r.x, b.x); FMA2(acc1b, r.y, b.y);
        }
        #pragma unroll
        for (int q = 0; q < NQ_RG; q++) {
            double2 a = h0p[NQ_SM + q];
            double2 b = h1p[NQ_SM + q];
            FMA2(acc0, rr[2 * q], a.x); FMA2(acc0b, rr[2 * q + 1], a.y);
            FMA2(acc1, rr[2 * q], b.x); FMA2(acc1b, rr[2 * q + 1], b.y);
        }

        float z0 = unpack_sum(acc0) + unpack_sum(acc0b);
        float z1 = unpack_sum(acc1) + unpack_sum(acc1b);

        float a0, a1;
        if ((tid >> 7) == 2) {               // g gate
            a0 = fast_tanh(z0); a1 = fast_tanh(z1);
        } else {                             // i, f, o gates
            a0 = fast_sigmoid(z0); a1 = fast_sigmoid(z1);
        }
        sact[tid] = a0;
        sact[NG + tid] = a1;
        __syncthreads();

        if (tid < 2 * U_) {
            int m = tid >> 7, u = tid & (U_ - 1);
            const float* s = sact + m * NG;
            float iv = s[u], fv = s[U_ + u], gv = s[2 * U_ + u], ov = s[3 * U_ + u];
            float c = fmaf(fv, sc[tid], iv * gv);
            float h = ov * fast_tanh(c);
            sc[tid] = c;
            sh[tid] = h;
            g_h[((size_t)(b0 + m) * T_ + t) * U_ + u] = h;
        }
        __syncthreads();
    }
}

// ---------------- dense head ----------------
__global__ void k_dense(const float* __restrict__ Wd, const float* __restrict__ bd,
                        float* __restrict__ out) {
    int idx = blockIdx.x * 256 + threadIdx.x;
    if (idx >= B_ * OUT_) return;
    int b = idx / OUT_, j = idx % OUT_;
    const float* hrow = &g_h[((size_t)b * T_ + (T_ - 1)) * U_];
    float s = bd[j];
    #pragma unroll
    for (int k = 0; k < U_; k++) s = fmaf(hrow[k], Wd[k * OUT_ + j], s);
    out[idx] = s;
}

// ---------------- launch ----------------
extern "C" void kernel_launch(void* const* d_in, const int* in_sizes, int n_in,
                              void* d_out, int out_size) {
    const float* x  = (const float*)d_in[0];
    const float* W0 = (const float*)d_in[1];
    const float* R0 = (const float*)d_in[2];
    const float* b0 = (const float*)d_in[3];
    const float* W1 = (const float*)d_in[4];
    const float* R1 = (const float*)d_in[5];
    const float* b1 = (const float*)d_in[6];
    const float* W2 = (const float*)d_in[7];
    const float* R2 = (const float*)d_in[8];
    const float* b2 = (const float*)d_in[9];
    const float* Wd = (const float*)d_in[10];
    const float* bd = (const float*)d_in[11];
    float* out = (float*)d_out;

    cudaFuncSetAttribute(k_lstm, cudaFuncAttributeMaxDynamicSharedMemorySize, LSTM_SMEM_BYTES);

    dim3 gemm_grid(NG / GBN, (B_ * T_) / GBM);

    k_transpose_R<<<NG, U_>>>(R0);
    k_gemm_xw<<<gemm_grid, 256>>>(x, W0, b0, F_);
    k_lstm<<<B_ / 2, 512, LSTM_SMEM_BYTES>>>();

    k_transpose_R<<<NG, U_>>>(R1);
    k_gemm_xw<<<gemm_grid, 256>>>(nullptr, W1, b1, U_);
    k_lstm<<<B_ / 2, 512, LSTM_SMEM_BYTES>>>();

    k_transpose_R<<<NG, U_>>>(R2);
    k_gemm_xw<<<gemm_grid, 256>>>(nullptr, W2, b2, U_);
    k_lstm<<<B_ / 2, 512, LSTM_SMEM_BYTES>>>();

    k_dense<<<(B_ * OUT_ + 255) / 256, 256>>>(Wd, bd, out);
}

// round 6
// speedup vs baseline: 4.9554x; 1.1317x over previous
#include <cuda_runtime.h>
#include <math.h>

// Problem constants
#define U_    128          // LSTM units
#define NG    512          // 4*U (gate width)
#define T_    512          // timesteps
#define B_    256          // batch
#define F_    64           // input features
#define OUT_  6            // dense head

// R split per gate column: 52 k-values in SMEM, 76 in registers
// stride 52*4=208B; lane pattern 208*l mod 128 hits 8 distinct 16B slots -> conflict-free
#define KSM   52
#define KRG   76
#define NQ_SM (KSM / 4)    // 13
#define NQ_RG (KRG / 4)    // 19

typedef unsigned long long ull;

#define FMA2U(acc, a, b) \
    asm("fma.rn.f32x2 %0, %1, %2, %0;" : "+l"(acc) : "l"(a), "l"(b))
#define FMA2(acc, a, b) \
    asm("fma.rn.f32x2 %0, %1, %2, %0;" : "+l"(acc) \
        : "l"(__double_as_longlong(a)), "l"(__double_as_longlong(b)))

__device__ __forceinline__ ull dup2(float x) {
    ull r;
    asm("mov.b64 %0, {%1, %1};" : "=l"(r) : "f"(x));
    return r;
}
__device__ __forceinline__ float lo32(ull v) { return __int_as_float((int)(v & 0xffffffffull)); }
__device__ __forceinline__ float hi32(ull v) { return __int_as_float((int)(v >> 32)); }
__device__ __forceinline__ float unpack_sum(ull v) { return lo32(v) + hi32(v); }

__device__ __forceinline__ float fast_sigmoid(float x) {
    return __fdividef(1.f, 1.f + __expf(-x));
}
__device__ __forceinline__ float fast_tanh(float x) {
    float e = __expf(fminf(-2.f * x, 80.f));
    return __fdividef(1.f - e, 1.f + e);
}

// ---------------- scratch ----------------
__device__ float g_xw[(size_t)B_ * T_ * NG];
__device__ float g_h [(size_t)B_ * T_ * U_];
__device__ float g_RT[NG * U_];

// ---------------- R transpose ----------------
__global__ void k_transpose_R(const float* __restrict__ R) {
    int j = blockIdx.x;
    int k = threadIdx.x;
    g_RT[j * U_ + k] = R[k * NG + j];
}

// ---------------- GEMM (unchanged R4) ----------------
#define GBM 128
#define GBN 128
#define GBK 8
#define GPAD 4
__global__ __launch_bounds__(256) void k_gemm_xw(const float* __restrict__ Ain,
                                                 const float* __restrict__ W,
                                                 const float* __restrict__ bias,
                                                 int K) {
    const float* A = Ain ? Ain : g_h;
    __shared__ float As[GBK][GBM + GPAD];
    __shared__ float Bs[GBK][GBN + GPAD];
    const int brow = blockIdx.y * GBM;
    const int bcol = blockIdx.x * GBN;
    const int tid = threadIdx.x;
    const int tx = tid & 15;
    const int ty = tid >> 4;

    const int a_m  = tid >> 1;
    const int a_kq = (tid & 1) * 4;
    const int b_k  = tid >> 5;
    const int b_n  = (tid & 31) * 4;

    ull acc2[8][4];
    #pragma unroll
    for (int i = 0; i < 8; i++)
        #pragma unroll
        for (int j = 0; j < 4; j++) acc2[i][j] = 0ull;

    for (int k0 = 0; k0 < K; k0 += GBK) {
        float4 av = *reinterpret_cast<const float4*>(&A[(size_t)(brow + a_m) * K + (k0 + a_kq)]);
        As[a_kq + 0][a_m] = av.x;
        As[a_kq + 1][a_m] = av.y;
        As[a_kq + 2][a_m] = av.z;
        As[a_kq + 3][a_m] = av.w;
        *reinterpret_cast<float4*>(&Bs[b_k][b_n]) =
            *reinterpret_cast<const float4*>(&W[(size_t)(k0 + b_k) * NG + (bcol + b_n)]);
        __syncthreads();

        #pragma unroll
        for (int k = 0; k < GBK; k++) {
            float4 a0 = *reinterpret_cast<const float4*>(&As[k][ty * 8]);
            float4 a1 = *reinterpret_cast<const float4*>(&As[k][ty * 8 + 4]);
            ulonglong2 bv0 = *reinterpret_cast<const ulonglong2*>(&Bs[k][tx * 8]);
            ulonglong2 bv1 = *reinterpret_cast<const ulonglong2*>(&Bs[k][tx * 8 + 4]);
            ull ad;
            ad = dup2(a0.x);
            FMA2U(acc2[0][0], ad, bv0.x); FMA2U(acc2[0][1], ad, bv0.y);
            FMA2U(acc2[0][2], ad, bv1.x); FMA2U(acc2[0][3], ad, bv1.y);
            ad = dup2(a0.y);
            FMA2U(acc2[1][0], ad, bv0.x); FMA2U(acc2[1][1], ad, bv0.y);
            FMA2U(acc2[1][2], ad, bv1.x); FMA2U(acc2[1][3], ad, bv1.y);
            ad = dup2(a0.z);
            FMA2U(acc2[2][0], ad, bv0.x); FMA2U(acc2[2][1], ad, bv0.y);
            FMA2U(acc2[2][2], ad, bv1.x); FMA2U(acc2[2][3], ad, bv1.y);
            ad = dup2(a0.w);
            FMA2U(acc2[3][0], ad, bv0.x); FMA2U(acc2[3][1], ad, bv0.y);
            FMA2U(acc2[3][2], ad, bv1.x); FMA2U(acc2[3][3], ad, bv1.y);
            ad = dup2(a1.x);
            FMA2U(acc2[4][0], ad, bv0.x); FMA2U(acc2[4][1], ad, bv0.y);
            FMA2U(acc2[4][2], ad, bv1.x); FMA2U(acc2[4][3], ad, bv1.y);
            ad = dup2(a1.y);
            FMA2U(acc2[5][0], ad, bv0.x); FMA2U(acc2[5][1], ad, bv0.y);
            FMA2U(acc2[5][2], ad, bv1.x); FMA2U(acc2[5][3], ad, bv1.y);
            ad = dup2(a1.z);
            FMA2U(acc2[6][0], ad, bv0.x); FMA2U(acc2[6][1], ad, bv0.y);
            FMA2U(acc2[6][2], ad, bv1.x); FMA2U(acc2[6][3], ad, bv1.y);
            ad = dup2(a1.w);
            FMA2U(acc2[7][0], ad, bv0.x); FMA2U(acc2[7][1], ad, bv0.y);
            FMA2U(acc2[7][2], ad, bv1.x); FMA2U(acc2[7][3], ad, bv1.y);
        }
        __syncthreads();
    }

    const int col0 = bcol + tx * 8;
    float bb[8];
    #pragma unroll
    for (int j = 0; j < 8; j++) bb[j] = bias[col0 + j];
    #pragma unroll
    for (int i = 0; i < 8; i++) {
        size_t row = (size_t)(brow + ty * 8 + i);
        float4 o0, o1;
        o0.x = lo32(acc2[i][0]) + bb[0]; o0.y = hi32(acc2[i][0]) + bb[1];
        o0.z = lo32(acc2[i][1]) + bb[2]; o0.w = hi32(acc2[i][1]) + bb[3];
        o1.x = lo32(acc2[i][2]) + bb[4]; o1.y = hi32(acc2[i][2]) + bb[5];
        o1.z = lo32(acc2[i][3]) + bb[6]; o1.w = hi32(acc2[i][3]) + bb[7];
        *reinterpret_cast<float4*>(&g_xw[row * NG + col0])     = o0;
        *reinterpret_cast<float4*>(&g_xw[row * NG + col0 + 4]) = o1;
    }
}

// ---------------- LSTM scan: 256 threads, 2 cols x 2 rows per thread ----------------
#define LSTM_SMEM_FLOATS (NG * KSM + 2 * U_ + 2 * U_ + 2 * NG)
#define LSTM_SMEM_BYTES  (LSTM_SMEM_FLOATS * 4)

__global__ __launch_bounds__(256) void k_lstm() {
    extern __shared__ float smem[];
    float* sR   = smem;                       // [512][KSM]
    float* sh   = sR + NG * KSM;              // [2][128]
    float* sc   = sh + 2 * U_;                // [2][128]
    float* sact = sc + 2 * U_;                // [2][512]

    const int tid = threadIdx.x;              // 0..255
    const int c0 = tid;                       // gate col (i or f gate)
    const int c1 = tid + 256;                 // gate col (g or o gate)
    const int b0 = blockIdx.x * 2;

    for (int i = tid; i < NG * KSM; i += 256) {
        int col = i / KSM, k = i - col * KSM;
        sR[i] = g_RT[col * U_ + k];
    }
    // register-resident R tails for both columns
    double rr0[NQ_RG * 2], rr1[NQ_RG * 2];
    {
        const double2* rg0 = reinterpret_cast<const double2*>(g_RT + c0 * U_ + KSM);
        const double2* rg1 = reinterpret_cast<const double2*>(g_RT + c1 * U_ + KSM);
        #pragma unroll
        for (int q = 0; q < NQ_RG; q++) {
            double2 v0 = rg0[q];
            double2 v1 = rg1[q];
            rr0[2 * q] = v0.x; rr0[2 * q + 1] = v0.y;
            rr1[2 * q] = v1.x; rr1[2 * q + 1] = v1.y;
        }
    }
    { sh[tid] = 0.f; sc[tid] = 0.f; }         // 256 = 2*U_ exactly
    __syncthreads();

    const double2* rs0 = reinterpret_cast<const double2*>(sR + c0 * KSM);
    const double2* rs1 = reinterpret_cast<const double2*>(sR + c1 * KSM);
    const double2* h0p = reinterpret_cast<const double2*>(sh);
    const double2* h1p = reinterpret_cast<const double2*>(sh + U_);
    const size_t xw0base = (size_t)b0 * T_ * NG;
    const size_t xw1base = (size_t)(b0 + 1) * T_ * NG;

    float pf00 = __ldcs(&g_xw[xw0base + c0]);
    float pf01 = __ldcs(&g_xw[xw0base + c1]);
    float pf10 = __ldcs(&g_xw[xw1base + c0]);
    float pf11 = __ldcs(&g_xw[xw1base + c1]);

    for (int t = 0; t < T_; t++) {
        ull a00 = (ull)__float_as_uint(pf00);   // row0, c0
        ull a01 = (ull)__float_as_uint(pf01);   // row0, c1
        ull a10 = (ull)__float_as_uint(pf10);   // row1, c0
        ull a11 = (ull)__float_as_uint(pf11);   // row1, c1
        if (t + 1 < T_) {
            size_t o0 = xw0base + (size_t)(t + 1) * NG;
            size_t o1 = xw1base + (size_t)(t + 1) * NG;
            pf00 = __ldcs(&g_xw[o0 + c0]);
            pf01 = __ldcs(&g_xw[o0 + c1]);
            pf10 = __ldcs(&g_xw[o1 + c0]);
            pf11 = __ldcs(&g_xw[o1 + c1]);
        }

        #pragma unroll
        for (int q = 0; q < NQ_SM; q++) {
            double2 r0 = rs0[q];
            double2 r1 = rs1[q];
            double2 h0 = h0p[q];
            double2 h1 = h1p[q];
            FMA2(a00, r0.x, h0.x); FMA2(a01, r1.x, h0.x);
            FMA2(a10, r0.x, h1.x); FMA2(a11, r1.x, h1.x);
            FMA2(a00, r0.y, h0.y); FMA2(a01, r1.y, h0.y);
            FMA2(a10, r0.y, h1.y); FMA2(a11, r1.y, h1.y);
        }
        #pragma unroll
        for (int q = 0; q < NQ_RG; q++) {
            double2 h0 = h0p[NQ_SM + q];
            double2 h1 = h1p[NQ_SM + q];
            FMA2(a00, rr0[2 * q], h0.x); FMA2(a01, rr1[2 * q], h0.x);
            FMA2(a10, rr0[2 * q], h1.x); FMA2(a11, rr1[2 * q], h1.x);
            FMA2(a00, rr0[2 * q + 1], h0.y); FMA2(a01, rr1[2 * q + 1], h0.y);
            FMA2(a10, rr0[2 * q + 1], h1.y); FMA2(a11, rr1[2 * q + 1], h1.y);
        }

        float z00 = unpack_sum(a00);
        float z01 = unpack_sum(a01);
        float z10 = unpack_sum(a10);
        float z11 = unpack_sum(a11);

        // c0 is gate i (tid<128) or f (tid>=128): always sigmoid, no branch
        float s00 = fast_sigmoid(z00);
        float s10 = fast_sigmoid(z10);
        // c1 is gate g (tid<128, tanh) or o (tid>=128, sigmoid): warp-uniform branch
        float s01, s11;
        if (tid < 128) { s01 = fast_tanh(z01);    s11 = fast_tanh(z11); }
        else           { s01 = fast_sigmoid(z01); s11 = fast_sigmoid(z11); }

        sact[c0] = s00;        sact[c1] = s01;
        sact[NG + c0] = s10;   sact[NG + c1] = s11;
        __syncthreads();

        {   // cell update: all 256 threads (2 rows x 128 units)
            int m = tid >> 7, u = tid & (U_ - 1);
            const float* s = sact + m * NG;
            float iv = s[u], fv = s[U_ + u], gv = s[2 * U_ + u], ov = s[3 * U_ + u];
            float c = fmaf(fv, sc[tid], iv * gv);
            float h = ov * fast_tanh(c);
            sc[tid] = c;
            sh[tid] = h;
            g_h[((size_t)(b0 + m) * T_ + t) * U_ + u] = h;
        }
        __syncthreads();
    }
}

// ---------------- dense head ----------------
__global__ void k_dense(const float* __restrict__ Wd, const float* __restrict__ bd,
                        float* __restrict__ out) {
    int idx = blockIdx.x * 256 + threadIdx.x;
    if (idx >= B_ * OUT_) return;
    int b = idx / OUT_, j = idx % OUT_;
    const float* hrow = &g_h[((size_t)b * T_ + (T_ - 1)) * U_];
    float s = bd[j];
    #pragma unroll
    for (int k = 0; k < U_; k++) s = fmaf(hrow[k], Wd[k * OUT_ + j], s);
    out[idx] = s;
}

// ---------------- launch ----------------
extern "C" void kernel_launch(void* const* d_in, const int* in_sizes, int n_in,
                              void* d_out, int out_size) {
    const float* x  = (const float*)d_in[0];
    const float* W0 = (const float*)d_in[1];
    const float* R0 = (const float*)d_in[2];
    const float* b0 = (const float*)d_in[3];
    const float* W1 = (const float*)d_in[4];
    const float* R1 = (const float*)d_in[5];
    const float* b1 = (const float*)d_in[6];
    const float* W2 = (const float*)d_in[7];
    const float* R2 = (const float*)d_in[8];
    const float* b2 = (const float*)d_in[9];
    const float* Wd = (const float*)d_in[10];
    const float* bd = (const float*)d_in[11];
    float* out = (float*)d_out;

    cudaFuncSetAttribute(k_lstm, cudaFuncAttributeMaxDynamicSharedMemorySize, LSTM_SMEM_BYTES);

    dim3 gemm_grid(NG / GBN, (B_ * T_) / GBM);

    k_transpose_R<<<NG, U_>>>(R0);
    k_gemm_xw<<<gemm_grid, 256>>>(x, W0, b0, F_);
    k_lstm<<<B_ / 2, 256, LSTM_SMEM_BYTES>>>();

    k_transpose_R<<<NG, U_>>>(R1);
    k_gemm_xw<<<gemm_grid, 256>>>(nullptr, W1, b1, U_);
    k_lstm<<<B_ / 2, 256, LSTM_SMEM_BYTES>>>();

    k_transpose_R<<<NG, U_>>>(R2);
    k_gemm_xw<<<gemm_grid, 256>>>(nullptr, W2, b2, U_);
    k_lstm<<<B_ / 2, 256, LSTM_SMEM_BYTES>>>();

    k_dense<<<(B_ * OUT_ + 255) / 256, 256>>>(Wd, bd, out);
}